// round 13
// baseline (speedup 1.0000x reference)
#include <cuda_runtime.h>
#include <cuda_fp16.h>

#define TN 400
#define PN 4000
#define NBLK 304          // 152 SMs x 2 co-resident blocks
#define TPB 416           // 13 warps; threads 0..399 own one target each
#define MAXP 15           // >= ceil(PN/NBLK)+1
#define ROW 36            // 32-bit slots per pred row

// dynamic smem layout (floats):
//   stg  [0 .. 21200)           staged tkp (400 x 53), fp32
//   sraw [21200 .. 22000)       staged raw pred rows (<=15 x 53)
//   ptile[22000 .. +MAXP*ROW)   preprocessed pred rows
#define STG_OFF   0
#define SRAW_OFF  21200
#define PTILE_OFF 22000
#define SMEM_FLOATS (PTILE_OFF + MAXP * ROW)
#define SMEM_BYTES  (SMEM_FLOATS * 4)

// pred row (36 x 32-bit slots):
//   u[0..16]  half2 {x,y} of kp0..16    u[17..19] 0
//   u[20..28] half2 Vp pairs {(0,1),(2,3),...,(14,15),(16,0)}   u[29..31] 0
//   f[32..35] fp32 {cp0, cp1, p0-p1, spp}

__device__ __forceinline__ __half2 u2h(unsigned u) {
    __half2 h; *reinterpret_cast<unsigned*>(&h) = u; return h;
}
__device__ __forceinline__ unsigned h2u(__half2 h) {
    return *reinterpret_cast<unsigned*>(&h);
}

__global__ __launch_bounds__(TPB, 2)
void matcher_kernel(const float* __restrict__ logits,   // [PN,2]
                    const float* __restrict__ pkp,      // [PN,53]
                    const int*   __restrict__ tids,     // [TN]
                    const float* __restrict__ tkp,      // [TN,53]
                    const int*   __restrict__ nbp,      // scalar num_boxes
                    float*       __restrict__ out)      // [PN,TN]
{
    extern __shared__ __align__(16) float dsm[];
    float* stg   = dsm + STG_OFF;
    float* sraw  = dsm + SRAW_OFF;
    float* ptile = dsm + PTILE_OFF;

    const int b = blockIdx.x;
    const int pbase = (b * PN) / NBLK;
    const int npred = ((b + 1) * PN) / NBLK - pbase;
    const int tid = threadIdx.x;
    const bool act = (tid < TN);
    const int tl = act ? tid : 0;

    int nbi = *nbp;
    float nb = (nbi > 0 && nbi < (1 << 20)) ? (float)nbi : *(const float*)nbp;
    const float inb = 1.0f / nb;

    // ---- coalesced staging: targets (float4) + this block's raw preds ----
    {
        const float4* src = (const float4*)tkp;       // 21200 floats = 5300 float4
        float4* dst = (float4*)stg;
        #pragma unroll
        for (int i = 0; i < 13; ++i) {
            int idx = tid + i * TPB;
            if (idx < 5300) dst[idx] = src[idx];
        }
        const int nraw = npred * 53;
        const float* ps = pkp + pbase * 53;
        for (int i = tid; i < nraw; i += TPB) sraw[i] = ps[i];
    }
    __syncthreads();

    // ---- ptile fill (fp32 -> half2), parallel across all threads ----
    {
        const int total = npred * ROW;
        for (int idx = tid; idx < total; idx += TPB) {
            const int r = idx / ROW;
            const int s = idx - r * ROW;
            if (s >= 32) continue;                    // fp32 scalar slots
            const float* kp = sraw + r * 53;
            unsigned val = 0u;
            if (s < 17) {                             // kp j = s: {x, y}
                val = h2u(__floats2half2_rn(kp[2 + 2 * s], kp[3 + 2 * s]));
            } else if (s >= 20 && s < 28) {           // Vp pairs (2i, 2i+1)
                const int i = s - 20;
                val = h2u(__floats2half2_rn(kp[36 + 2 * i], kp[37 + 2 * i]));
            } else if (s == 28) {                     // (V16, 0)
                val = h2u(__floats2half2_rn(kp[52], 0.0f));
            }
            ((unsigned*)(ptile + r * ROW))[s] = val;
        }
    }
    // ---- per-pred fp32 scalars (threads 0..npred-1) ----
    if (tid < npred) {
        const int gp = pbase + tid;
        const float l0 = logits[gp * 2 + 0];
        const float l1 = logits[gp * 2 + 1];
        const float m  = fmaxf(l0, l1);
        const float e0 = __expf(l0 - m);
        const float e1 = __expf(l1 - m);
        const float inv = 1.0f / (e0 + e1);
        const float p0 = e0 * inv, p1 = e1 * inv;

        const float* kp = sraw + tid * 53;
        const float c0 = kp[0], c1 = kp[1];
        float sv = 0.0f;
        #pragma unroll
        for (int j = 0; j < 17; ++j) { float v = kp[36 + j]; sv = fmaf(v, v, sv); }
        float* sp = ptile + tid * ROW;
        sp[32] = c0;
        sp[33] = c1;
        sp[34] = p0 - p1;
        sp[35] = 0.2f * inb * sv + 0.5f * inb * (c0 * c0 + c1 * c1) - p0;  // spp
    }

    // ---- per-thread target state: all 17 keypoints (half2) ----
    const float* tk = stg + tl * 53;
    const float cg0 = tk[0], cg1 = tk[1];
    __half2 nzg[17];           // {-Zg_x, -Zg_y} per kp
    __half2 w2[17];            // {0.5*inb*Vg, same}
    __half2 wv2[9];            // viz pairs {w_2i, w_2i+1}
    float wj[17];
    #pragma unroll
    for (int j = 0; j < 17; ++j) {
        nzg[j] = __floats2half2_rn(-tk[2 + 2 * j], -tk[3 + 2 * j]);
        wj[j]  = 0.5f * inb * tk[36 + j];
        w2[j]  = __half2half2(__float2half_rn(wj[j]));
    }
    #pragma unroll
    for (int i = 0; i < 8; ++i)
        wv2[i] = __floats2half2_rn(wj[2 * i], wj[2 * i + 1]);
    wv2[8] = __floats2half2_rn(wj[16], 0.0f);
    const __half2 eight2 = __half2half2(__float2half_rn(8.0f));
    const float ncgx = -cg0, ncgy = -cg1;
    float sv = 0.0f;
    #pragma unroll
    for (int j = 0; j < 17; ++j) { float v = tk[36 + j]; sv = fmaf(v, v, sv); }
    const float sgt = 0.2f * inb * sv + 0.5f * inb * (cg0 * cg0 + cg1 * cg1);
    const float tcx = -inb * cg0;
    const float tcy = -inb * cg1;
    const float idf = (float)tids[tl];
    __syncthreads();

    auto compute = [&](const float* pp) -> float {
        const unsigned* ru = (const unsigned*)pp;
        const float4 h4 = *(const float4*)(pp + 32);   // cp0, cp1, p0-p1, spp
        const __half2 dc = __floats2half2_rn(h4.x + ncgx, h4.y + ncgy);

        const uint4 z0 = *(const uint4*)(ru);          // kp 0..3
        const uint4 z1 = *(const uint4*)(ru + 4);      // kp 4..7
        const uint4 z2 = *(const uint4*)(ru + 8);      // kp 8..11
        const uint4 z3 = *(const uint4*)(ru + 12);     // kp 12..15
        const unsigned z16 = ru[16];

        __half2 acc0 = __floats2half2_rn(0.0f, 0.0f);
        __half2 acc1 = __floats2half2_rn(0.0f, 0.0f);
        #define KP(zr, i, A) do {                                          \
            __half2 z  = u2h(zr);                                          \
            __half2 dz = __hadd2(z, nzg[i]);                               \
            __half2 t  = __hadd2(dz, dc);                                  \
            __half2 c  = __hfma2(__habs2(t), eight2, __habs2(dz));         \
            A = __hfma2(c, w2[i], A);                                      \
        } while (0)
        KP(z0.x,  0, acc0); KP(z0.y,  1, acc1); KP(z0.z,  2, acc0); KP(z0.w,  3, acc1);
        KP(z1.x,  4, acc0); KP(z1.y,  5, acc1); KP(z1.z,  6, acc0); KP(z1.w,  7, acc1);
        KP(z2.x,  8, acc0); KP(z2.y,  9, acc1); KP(z2.z, 10, acc0); KP(z2.w, 11, acc1);
        KP(z3.x, 12, acc0); KP(z3.y, 13, acc1); KP(z3.z, 14, acc0); KP(z3.w, 15, acc1);
        KP(z16,  16, acc0);
        #undef KP

        // viz dot (half2 pairs)
        const uint4 vA = *(const uint4*)(ru + 20);
        const uint4 vB = *(const uint4*)(ru + 24);
        const unsigned v16 = ru[28];
        __half2 dv2 = __hmul2(u2h(vA.x), wv2[0]);
        dv2 = __hfma2(u2h(vA.y), wv2[1], dv2);
        dv2 = __hfma2(u2h(vA.z), wv2[2], dv2);
        dv2 = __hfma2(u2h(vA.w), wv2[3], dv2);
        dv2 = __hfma2(u2h(vB.x), wv2[4], dv2);
        dv2 = __hfma2(u2h(vB.y), wv2[5], dv2);
        dv2 = __hfma2(u2h(vB.z), wv2[6], dv2);
        dv2 = __hfma2(u2h(vB.w), wv2[7], dv2);
        dv2 = __hfma2(u2h(v16),  wv2[8], dv2);

        const float2 af  = __half22float2(__hadd2(acc0, acc1));
        const float2 dvf = __half22float2(dv2);
        float res = af.x + af.y;                  // 0.5*offset + 4*abs terms
        res = fmaf(dvf.x + dvf.y, -0.8f, res);    // viz cross
        res = fmaf(h4.x, tcx, res);               // center cross x
        res = fmaf(h4.y, tcy, res);               // center cross y
        res = fmaf(h4.z, idf, res);               // class id*(p0-p1)
        return res + h4.w + sgt;                  // pred + target constants
    };

    int p = 0;
    for (; p + 1 < npred; p += 2) {
        float r0 = compute(ptile + p * ROW);
        float r1 = compute(ptile + (p + 1) * ROW);
        if (act) {
            float* o = out + (size_t)(pbase + p) * TN + tid;
            o[0]  = r0;
            o[TN] = r1;
        }
    }
    if (p < npred) {
        float r0 = compute(ptile + p * ROW);
        if (act)
            out[(size_t)(pbase + p) * TN + tid] = r0;
    }
}

extern "C" void kernel_launch(void* const* d_in, const int* in_sizes, int n_in,
                              void* d_out, int out_size)
{
    const float* logits = (const float*)d_in[0];   // pred_logits   [8,500,2]
    const float* pkp    = (const float*)d_in[1];   // pred_keypoints[8,500,53]
    const int*   tids   = (const int*)  d_in[2];   // tgt_ids       [400]
    const float* tkp    = (const float*)d_in[3];   // tgt_keypoints [400,53]
    const int*   nbp    = (const int*)  d_in[4];   // num_boxes scalar
    (void)in_sizes; (void)n_in; (void)out_size;

    static int smem_set = 0;
    if (!smem_set) {
        cudaFuncSetAttribute(matcher_kernel,
                             cudaFuncAttributeMaxDynamicSharedMemorySize, SMEM_BYTES);
        smem_set = 1;
    }
    matcher_kernel<<<NBLK, TPB, SMEM_BYTES>>>(logits, pkp, tids, tkp, nbp,
                                              (float*)d_out);
}

// round 14
// speedup vs baseline: 1.1214x; 1.1214x over previous
#include <cuda_runtime.h>
#include <cuda_fp16.h>

#define TN 400
#define PN 4000
#define NBLOCKS 152       // one block per GB300 SM
#define TPB 832           // 26 warps = 2 groups x 13 warps (416 thr, 400 targets)
#define GW  416
#define MAXP 28           // >= ceil(PN/NBLOCKS)+1
#define ROW 36            // 32-bit slots per pred row

// dynamic smem layout (floats):
//   stg  [0 .. 21200)           staged tkp (400 x 53), fp32
//   sraw [21200 .. 22688)       staged raw pred rows (<=28 x 53)
//   ptile[22688 .. +MAXP*ROW)   preprocessed pred rows
#define STG_OFF   0
#define SRAW_OFF  21200
#define PTILE_OFF 22688
#define SMEM_FLOATS (PTILE_OFF + MAXP * ROW)
#define SMEM_BYTES  (SMEM_FLOATS * 4)

// pred row (36 x 32-bit slots):
//   u[0..16]  half2 {x,y} of kp0..16    u[17..19] 0
//   u[20..28] half2 Vp pairs {(0,1)..(14,15),(16,0)}   u[29..31] 0
//   f[32..35] fp32 {cp0, cp1, p0-p1, spp}

__device__ __forceinline__ __half2 u2h(unsigned u) {
    __half2 h; *reinterpret_cast<unsigned*>(&h) = u; return h;
}
__device__ __forceinline__ unsigned h2u(__half2 h) {
    return *reinterpret_cast<unsigned*>(&h);
}

__global__ __launch_bounds__(TPB, 1)
void matcher_kernel(const float* __restrict__ logits,   // [PN,2]
                    const float* __restrict__ pkp,      // [PN,53]
                    const int*   __restrict__ tids,     // [TN]
                    const float* __restrict__ tkp,      // [TN,53]
                    const int*   __restrict__ nbp,      // scalar num_boxes
                    float*       __restrict__ out)      // [PN,TN]
{
    extern __shared__ __align__(16) float dsm[];
    float* stg   = dsm + STG_OFF;
    float* sraw  = dsm + SRAW_OFF;
    float* ptile = dsm + PTILE_OFF;

    const int b = blockIdx.x;
    const int pbase = (b * PN) / NBLOCKS;
    const int npred = ((b + 1) * PN) / NBLOCKS - pbase;
    const int tid = threadIdx.x;
    const int g   = tid / GW;             // pred-half group 0/1
    const int ti  = tid - g * GW;         // 0..415
    const bool act = (ti < TN);
    const int tl = act ? ti : 0;

    int nbi = *nbp;
    float nb = (nbi > 0 && nbi < (1 << 20)) ? (float)nbi : *(const float*)nbp;
    const float inb = 1.0f / nb;

    // ---- coalesced staging (once per SM): targets + this block's raw preds ----
    {
        const float4* src = (const float4*)tkp;       // 21200 floats = 5300 float4
        float4* dst = (float4*)stg;
        #pragma unroll
        for (int i = 0; i < 7; ++i) {
            int idx = tid + i * TPB;
            if (idx < 5300) dst[idx] = src[idx];
        }
        const int nraw = npred * 53;
        const float* ps = pkp + pbase * 53;
        for (int i = tid; i < nraw; i += TPB) sraw[i] = ps[i];
    }
    __syncthreads();

    // ---- ptile fill (fp32 -> half2), parallel across all threads ----
    {
        const int total = npred * ROW;
        for (int idx = tid; idx < total; idx += TPB) {
            const int r = idx / ROW;
            const int s = idx - r * ROW;
            if (s >= 32) continue;                    // fp32 scalar slots
            const float* kp = sraw + r * 53;
            unsigned val = 0u;
            if (s < 17) {                             // kp j = s: {x, y}
                val = h2u(__floats2half2_rn(kp[2 + 2 * s], kp[3 + 2 * s]));
            } else if (s >= 20 && s < 28) {           // Vp pairs (2i, 2i+1)
                const int i = s - 20;
                val = h2u(__floats2half2_rn(kp[36 + 2 * i], kp[37 + 2 * i]));
            } else if (s == 28) {                     // (V16, 0)
                val = h2u(__floats2half2_rn(kp[52], 0.0f));
            }
            ((unsigned*)(ptile + r * ROW))[s] = val;
        }
    }
    // ---- per-pred fp32 scalars (threads 0..npred-1) ----
    if (tid < npred) {
        const int gp = pbase + tid;
        const float l0 = logits[gp * 2 + 0];
        const float l1 = logits[gp * 2 + 1];
        const float m  = fmaxf(l0, l1);
        const float e0 = __expf(l0 - m);
        const float e1 = __expf(l1 - m);
        const float inv = 1.0f / (e0 + e1);
        const float p0 = e0 * inv, p1 = e1 * inv;

        const float* kp = sraw + tid * 53;
        const float c0 = kp[0], c1 = kp[1];
        float sv = 0.0f;
        #pragma unroll
        for (int j = 0; j < 17; ++j) { float v = kp[36 + j]; sv = fmaf(v, v, sv); }
        float* sp = ptile + tid * ROW;
        sp[32] = c0;
        sp[33] = c1;
        sp[34] = p0 - p1;
        sp[35] = 0.2f * inb * sv + 0.5f * inb * (c0 * c0 + c1 * c1) - p0;  // spp
    }

    // ---- per-thread target state: all 17 keypoints (half2) ----
    const float* tk = stg + tl * 53;
    const float cg0 = tk[0], cg1 = tk[1];
    __half2 nzg[17];           // {-Zg_x, -Zg_y} per kp
    __half2 w2[17];            // {0.5*inb*Vg, same}
    __half2 wv2[9];            // viz pairs {w_2i, w_2i+1}
    float wj[17];
    #pragma unroll
    for (int j = 0; j < 17; ++j) {
        nzg[j] = __floats2half2_rn(-tk[2 + 2 * j], -tk[3 + 2 * j]);
        wj[j]  = 0.5f * inb * tk[36 + j];
        w2[j]  = __half2half2(__float2half_rn(wj[j]));
    }
    #pragma unroll
    for (int i = 0; i < 8; ++i)
        wv2[i] = __floats2half2_rn(wj[2 * i], wj[2 * i + 1]);
    wv2[8] = __floats2half2_rn(wj[16], 0.0f);
    const __half2 eight2 = __half2half2(__float2half_rn(8.0f));
    const float ncgx = -cg0, ncgy = -cg1;
    float sv = 0.0f;
    #pragma unroll
    for (int j = 0; j < 17; ++j) { float v = tk[36 + j]; sv = fmaf(v, v, sv); }
    const float sgt = 0.2f * inb * sv + 0.5f * inb * (cg0 * cg0 + cg1 * cg1);
    const float tcx = -inb * cg0;
    const float tcy = -inb * cg1;
    const float idf = (float)tids[tl];
    __syncthreads();

    auto compute = [&](const float* pp) -> float {
        const unsigned* ru = (const unsigned*)pp;
        const float4 h4 = *(const float4*)(pp + 32);   // cp0, cp1, p0-p1, spp
        const __half2 dc = __floats2half2_rn(h4.x + ncgx, h4.y + ncgy);

        const uint4 z0 = *(const uint4*)(ru);          // kp 0..3
        const uint4 z1 = *(const uint4*)(ru + 4);      // kp 4..7
        const uint4 z2 = *(const uint4*)(ru + 8);      // kp 8..11
        const uint4 z3 = *(const uint4*)(ru + 12);     // kp 12..15
        const unsigned z16 = ru[16];

        __half2 acc0 = __floats2half2_rn(0.0f, 0.0f);
        __half2 acc1 = __floats2half2_rn(0.0f, 0.0f);
        #define KP(zr, i, A) do {                                          \
            __half2 z  = u2h(zr);                                          \
            __half2 dz = __hadd2(z, nzg[i]);                               \
            __half2 t  = __hadd2(dz, dc);                                  \
            __half2 c  = __hfma2(__habs2(t), eight2, __habs2(dz));         \
            A = __hfma2(c, w2[i], A);                                      \
        } while (0)
        KP(z0.x,  0, acc0); KP(z0.y,  1, acc1); KP(z0.z,  2, acc0); KP(z0.w,  3, acc1);
        KP(z1.x,  4, acc0); KP(z1.y,  5, acc1); KP(z1.z,  6, acc0); KP(z1.w,  7, acc1);
        KP(z2.x,  8, acc0); KP(z2.y,  9, acc1); KP(z2.z, 10, acc0); KP(z2.w, 11, acc1);
        KP(z3.x, 12, acc0); KP(z3.y, 13, acc1); KP(z3.z, 14, acc0); KP(z3.w, 15, acc1);
        KP(z16,  16, acc0);
        #undef KP

        // viz dot (half2 pairs)
        const uint4 vA = *(const uint4*)(ru + 20);
        const uint4 vB = *(const uint4*)(ru + 24);
        const unsigned v16 = ru[28];
        __half2 dv2 = __hmul2(u2h(vA.x), wv2[0]);
        dv2 = __hfma2(u2h(vA.y), wv2[1], dv2);
        dv2 = __hfma2(u2h(vA.z), wv2[2], dv2);
        dv2 = __hfma2(u2h(vA.w), wv2[3], dv2);
        dv2 = __hfma2(u2h(vB.x), wv2[4], dv2);
        dv2 = __hfma2(u2h(vB.y), wv2[5], dv2);
        dv2 = __hfma2(u2h(vB.z), wv2[6], dv2);
        dv2 = __hfma2(u2h(vB.w), wv2[7], dv2);
        dv2 = __hfma2(u2h(v16),  wv2[8], dv2);

        const float2 af  = __half22float2(__hadd2(acc0, acc1));
        const float2 dvf = __half22float2(dv2);
        float res = af.x + af.y;                  // 0.5*offset + 4*abs terms
        res = fmaf(dvf.x + dvf.y, -0.8f, res);    // viz cross
        res = fmaf(h4.x, tcx, res);               // center cross x
        res = fmaf(h4.y, tcy, res);               // center cross y
        res = fmaf(h4.z, idf, res);               // class id*(p0-p1)
        return res + h4.w + sgt;                  // pred + target constants
    };

    // ---- pred range for this group ----
    const int nh  = (npred + 1) >> 1;
    const int pLo = g ? nh : 0;
    const int pHi = g ? npred : nh;

    int p = pLo;
    for (; p + 1 < pHi; p += 2) {
        float r0 = compute(ptile + p * ROW);
        float r1 = compute(ptile + (p + 1) * ROW);
        if (act) {
            float* o = out + (size_t)(pbase + p) * TN + tl;
            o[0]  = r0;
            o[TN] = r1;
        }
    }
    if (p < pHi) {
        float r0 = compute(ptile + p * ROW);
        if (act)
            out[(size_t)(pbase + p) * TN + tl] = r0;
    }
}

extern "C" void kernel_launch(void* const* d_in, const int* in_sizes, int n_in,
                              void* d_out, int out_size)
{
    const float* logits = (const float*)d_in[0];   // pred_logits   [8,500,2]
    const float* pkp    = (const float*)d_in[1];   // pred_keypoints[8,500,53]
    const int*   tids   = (const int*)  d_in[2];   // tgt_ids       [400]
    const float* tkp    = (const float*)d_in[3];   // tgt_keypoints [400,53]
    const int*   nbp    = (const int*)  d_in[4];   // num_boxes scalar
    (void)in_sizes; (void)n_in; (void)out_size;

    static int smem_set = 0;
    if (!smem_set) {
        cudaFuncSetAttribute(matcher_kernel,
                             cudaFuncAttributeMaxDynamicSharedMemorySize, SMEM_BYTES);
        smem_set = 1;
    }
    matcher_kernel<<<NBLOCKS, TPB, SMEM_BYTES>>>(logits, pkp, tids, tkp, nbp,
                                                 (float*)d_out);
}